// round 12
// baseline (speedup 1.0000x reference)
#include <cuda_runtime.h>
#include <cuda_bf16.h>

// Problem constants
#define BATCH   8
#define IN_P    16     // in_planes
#define REP_C   16     // PROD_DW / IN_PLANES
#define OUT_P   32     // out_planes
#define PV      256    // 32*32 pixels / 4 (float4 pixel-vecs)
#define C_X     256    // PROD_DW channels of x
#define C_OUT1  8192   // OUT_P * PROD_DW
#define O_PER_C 8      // o values per main block

#define OUT1_FLOATS ((size_t)BATCH * C_OUT1 * 1024)

// 256-bit streaming store (Blackwell STG.256)
__device__ __forceinline__ void stg256_cs(float* p,
    float v0, float v1, float v2, float v3,
    float v4, float v5, float v6, float v7)
{
    asm volatile("st.global.cs.v8.f32 [%0], {%1,%2,%3,%4,%5,%6,%7,%8};"
                 :: "l"(p), "f"(v0), "f"(v1), "f"(v2), "f"(v3),
                    "f"(v4), "f"(v5), "f"(v6), "f"(v7) : "memory");
}

// Main blocks (0..511): (b, i, o-chunk-of-8), 128 threads. Each thread owns 8
// contiguous pixels (floats 8t..8t+7) and ALL 16 rep-channels in registers
// (128 x-regs). Gate bits computed o-outer with the exact reference rounding
// (sequential sum of PRODUCTS w*x_r, r=0..15) — no smem handoff, no syncs.
// Store sweep uses STG.256: half the store instructions of the float4 version
// for identical bytes/coalescing.
// Tail blocks (512..519): the tiny dense relu(out2) path, peeled for uniformity.
__global__ __launch_bounds__(128, 3) void qconv_pw_kernel(
    const float4* __restrict__ x,      // (B,256,256) float4
    const float4* __restrict__ x2,     // (B,16,256)  float4
    const float*  __restrict__ w,      // (32,16)
    float* __restrict__ out)           // out1 floats then out2 floats
{
    const int tid = threadIdx.x;       // 0..127
    const int blk = blockIdx.x;

    __shared__ float ws[OUT_P * IN_P];
    #pragma unroll
    for (int k = 0; k < 4; k++)
        ws[tid + k * 128] = w[tid + k * 128];
    __syncthreads();

    if (blk >= BATCH * IN_P * 4) {
        // ---- out2 path: relu(einsum('bihw,oi->bohw')) for one batch ----
        const int b = blk - BATCH * IN_P * 4;
        float4* o4 = (float4*)(out + OUT1_FLOATS);
        #pragma unroll
        for (int half = 0; half < 2; half++) {
            const int p = half * 128 + tid;  // pixel-vec 0..255
            const float4* x2b = x2 + (size_t)b * IN_P * PV + p;
            float4 xv[IN_P];
            #pragma unroll
            for (int ii = 0; ii < IN_P; ii++)
                xv[ii] = __ldg(&x2b[(size_t)ii * PV]);
            #pragma unroll 4
            for (int o = 0; o < OUT_P; o++) {
                float ax = 0.f, ay = 0.f, az = 0.f, aw = 0.f;
                #pragma unroll
                for (int ii = 0; ii < IN_P; ii++) {   // sequential ii: einsum
                    const float wv = ws[o * IN_P + ii];
                    ax = fmaf(wv, xv[ii].x, ax);
                    ay = fmaf(wv, xv[ii].y, ay);
                    az = fmaf(wv, xv[ii].z, az);
                    aw = fmaf(wv, xv[ii].w, aw);
                }
                float4 r;
                r.x = fmaxf(ax, 0.f);
                r.y = fmaxf(ay, 0.f);
                r.z = fmaxf(az, 0.f);
                r.w = fmaxf(aw, 0.f);
                o4[((size_t)b * OUT_P + o) * PV + p] = r;
            }
        }
        return;
    }

    // ---- main out1 path ----
    const int oc = blk & 3;            // o-chunk (8 o each)
    const int i  = (blk >> 2) & 15;    // in-plane
    const int b  = blk >> 6;           // batch

    // Load ALL 16 rep-channels x 8 pixels for this thread (two float4 per r).
    const float4* xc = x + ((size_t)b * C_X + (size_t)i * REP_C) * PV + 2 * tid;
    float4 xa[REP_C], xb[REP_C];
    #pragma unroll
    for (int r = 0; r < REP_C; r++) {
        xa[r] = __ldg(&xc[(size_t)r * PV]);
        xb[r] = __ldg(&xc[(size_t)r * PV + 1]);
    }

    // Phase 1: gate bits. Byte c of the 64-bit mask = pixel 8t+c, bit oo.
    uint m_lo = 0u, m_hi = 0u;
    #pragma unroll
    for (int oo = 0; oo < O_PER_C; oo++) {
        const float wv = ws[(oc * O_PER_C + oo) * IN_P + i];
        float t0=0.f,t1=0.f,t2=0.f,t3=0.f,t4=0.f,t5=0.f,t6=0.f,t7=0.f;
        #pragma unroll
        for (int r = 0; r < REP_C; r++) {          // sequential r: ref order
            t0 += wv * xa[r].x;  t1 += wv * xa[r].y;
            t2 += wv * xa[r].z;  t3 += wv * xa[r].w;
            t4 += wv * xb[r].x;  t5 += wv * xb[r].y;
            t6 += wv * xb[r].z;  t7 += wv * xb[r].w;
        }
        m_lo |= (t0 > 0.f ? 1u : 0u) << (0*8 + oo);
        m_lo |= (t1 > 0.f ? 1u : 0u) << (1*8 + oo);
        m_lo |= (t2 > 0.f ? 1u : 0u) << (2*8 + oo);
        m_lo |= (t3 > 0.f ? 1u : 0u) << (3*8 + oo);
        m_hi |= (t4 > 0.f ? 1u : 0u) << (0*8 + oo);
        m_hi |= (t5 > 0.f ? 1u : 0u) << (1*8 + oo);
        m_hi |= (t6 > 0.f ? 1u : 0u) << (2*8 + oo);
        m_hi |= (t7 > 0.f ? 1u : 0u) << (3*8 + oo);
    }

    // Phase 2: STG.256 streaming-store sweep, 8 o x 16 r.
    float* ob = out + ((size_t)b * C_OUT1 + (size_t)i * REP_C) * 1024 + 8 * tid;
    #pragma unroll
    for (int oo = 0; oo < O_PER_C; oo++) {
        const int o = oc * O_PER_C + oo;
        const float wv = ws[o * IN_P + i];
        const float g0 = ((m_lo >> (0*8 + oo)) & 1u) ? wv : 0.f;
        const float g1 = ((m_lo >> (1*8 + oo)) & 1u) ? wv : 0.f;
        const float g2 = ((m_lo >> (2*8 + oo)) & 1u) ? wv : 0.f;
        const float g3 = ((m_lo >> (3*8 + oo)) & 1u) ? wv : 0.f;
        const float g4 = ((m_hi >> (0*8 + oo)) & 1u) ? wv : 0.f;
        const float g5 = ((m_hi >> (1*8 + oo)) & 1u) ? wv : 0.f;
        const float g6 = ((m_hi >> (2*8 + oo)) & 1u) ? wv : 0.f;
        const float g7 = ((m_hi >> (3*8 + oo)) & 1u) ? wv : 0.f;

        float* dst = ob + (size_t)o * (C_X * 1024);
        #pragma unroll
        for (int r = 0; r < REP_C; r++) {
            stg256_cs(dst + (size_t)r * 1024,
                      g0 * xa[r].x, g1 * xa[r].y, g2 * xa[r].z, g3 * xa[r].w,
                      g4 * xb[r].x, g5 * xb[r].y, g6 * xb[r].z, g7 * xb[r].w);
        }
    }
}

extern "C" void kernel_launch(void* const* d_in, const int* in_sizes, int n_in,
                              void* d_out, int out_size)
{
    const float4* x  = (const float4*)d_in[0];
    const float4* x2 = (const float4*)d_in[1];
    const float*  w  = (const float*) d_in[2];
    float* out = (float*)d_out;

    qconv_pw_kernel<<<BATCH * IN_P * 4 + BATCH, 128>>>(x, x2, w, out);
}

// round 17
// speedup vs baseline: 1.2464x; 1.2464x over previous
#include <cuda_runtime.h>
#include <cuda_bf16.h>

// Problem constants
#define BATCH   8
#define IN_P    16     // in_planes
#define REP_C   16     // PROD_DW / IN_PLANES
#define OUT_P   32     // out_planes
#define PV      256    // 32*32 pixels / 4 (float4 pixel-vecs)
#define C_X     256    // PROD_DW channels of x
#define C_OUT1  8192   // OUT_P * PROD_DW
#define O_PER_C 16     // o values per main block (o-half)

#define OUT1_VECS ((size_t)BATCH * C_OUT1 * PV)   // 16777216 float4

// Main blocks (0..255): (b, i, o-half-of-16), 256 threads = 1 pixel-vec each.
// 264 total blocks at 2 blocks/SM = ONE wave (no wave-2 tail). Each thread
// loads its 16 rep-channels of x ONCE (chip-wide x amp = 2x, 16 MB), computes
// 16 gate bits (reference rounding: sequential sum of the PRODUCTS w*x_r over
// r=0..15), then streams 16x16 perfectly-coalesced float4 stores.
// Tail blocks (256..263): the tiny dense relu(out2) path, one per batch.
__global__ __launch_bounds__(256) void qconv_pw_kernel(
    const float4* __restrict__ x,      // (B,256,1024) -> (B,256,256) float4
    const float4* __restrict__ x2,     // (B,16,1024)  -> (B,16,256)  float4
    const float*  __restrict__ w,      // (32,16)
    float4* __restrict__ out)          // out1 vecs then out2 vecs
{
    const int tid = threadIdx.x;
    const int blk = blockIdx.x;

    __shared__ float ws[OUT_P * IN_P];
    ws[tid] = w[tid];
    ws[tid + 256] = w[tid + 256];
    __syncthreads();

    if (blk >= BATCH * IN_P * 2) {
        // ---- out2 path: relu(einsum('bihw,oi->bohw')) for one batch ----
        const int b = blk - BATCH * IN_P * 2;
        const int p = tid;
        const float4* x2b = x2 + (size_t)b * IN_P * PV + p;

        float4 xv[IN_P];
        #pragma unroll
        for (int ii = 0; ii < IN_P; ii++)
            xv[ii] = __ldg(&x2b[(size_t)ii * PV]);

        #pragma unroll 4
        for (int o = 0; o < OUT_P; o++) {
            float ax = 0.f, ay = 0.f, az = 0.f, aw = 0.f;
            #pragma unroll
            for (int ii = 0; ii < IN_P; ii++) {   // sequential ii: einsum order
                const float wv = ws[o * IN_P + ii];
                ax = fmaf(wv, xv[ii].x, ax);
                ay = fmaf(wv, xv[ii].y, ay);
                az = fmaf(wv, xv[ii].z, az);
                aw = fmaf(wv, xv[ii].w, aw);
            }
            float4 r;
            r.x = fmaxf(ax, 0.f);
            r.y = fmaxf(ay, 0.f);
            r.z = fmaxf(az, 0.f);
            r.w = fmaxf(aw, 0.f);
            out[OUT1_VECS + ((size_t)b * OUT_P + o) * PV + p] = r;
        }
        return;
    }

    // ---- main out1 path ----
    const int oh = blk & 1;            // o-half (16 o each)
    const int i  = (blk >> 1) & 15;    // in-plane
    const int b  = blk >> 5;           // batch
    const int p  = tid;                // pixel-vec 0..255

    // Load the 16 rep-channels for this (b,i) pixel-vec; keep in registers.
    const float4* xc = x + ((size_t)b * C_X + (size_t)i * REP_C) * PV + p;
    float4 xr[REP_C];
    #pragma unroll
    for (int r = 0; r < REP_C; r++)
        xr[r] = __ldg(&xc[(size_t)r * PV]);

    // Phase 1: gate bits for the 16 o values (exact reference rounding:
    // sequential sum of the PRODUCTS w*x_r over r = 0..15).
    uint m_x = 0u, m_y = 0u, m_z = 0u, m_w = 0u;
    #pragma unroll
    for (int oo = 0; oo < O_PER_C; oo++) {
        const float wv = ws[(oh * O_PER_C + oo) * IN_P + i];
        float tx = 0.f, ty = 0.f, tz = 0.f, tw = 0.f;
        #pragma unroll
        for (int r = 0; r < REP_C; r++) {
            tx += wv * xr[r].x;
            ty += wv * xr[r].y;
            tz += wv * xr[r].z;
            tw += wv * xr[r].w;
        }
        m_x |= (tx > 0.f ? 1u : 0u) << oo;
        m_y |= (ty > 0.f ? 1u : 0u) << oo;
        m_z |= (tz > 0.f ? 1u : 0u) << oo;
        m_w |= (tw > 0.f ? 1u : 0u) << oo;
    }

    // Phase 2: streaming-store sweep, 16 o x 16 r.
    float4* ob = out + ((size_t)b * C_OUT1 + (size_t)i * REP_C) * PV + p;
    #pragma unroll 4
    for (int oo = 0; oo < O_PER_C; oo++) {
        const int o = oh * O_PER_C + oo;
        const float wv = ws[o * IN_P + i];
        const float gx = ((m_x >> oo) & 1u) ? wv : 0.f;
        const float gy = ((m_y >> oo) & 1u) ? wv : 0.f;
        const float gz = ((m_z >> oo) & 1u) ? wv : 0.f;
        const float gw = ((m_w >> oo) & 1u) ? wv : 0.f;

        float4* dst = ob + (size_t)o * (C_X * PV);
        #pragma unroll
        for (int r = 0; r < REP_C; r++) {
            float4 s;
            s.x = gx * xr[r].x;
            s.y = gy * xr[r].y;
            s.z = gz * xr[r].z;
            s.w = gw * xr[r].w;
            __stcs(&dst[(size_t)r * PV], s);   // streaming: never re-read
        }
    }
}

extern "C" void kernel_launch(void* const* d_in, const int* in_sizes, int n_in,
                              void* d_out, int out_size)
{
    const float4* x  = (const float4*)d_in[0];
    const float4* x2 = (const float4*)d_in[1];
    const float*  w  = (const float*) d_in[2];
    float4* out = (float4*)d_out;

    qconv_pw_kernel<<<BATCH * IN_P * 2 + BATCH, 256>>>(x, x2, w, out);
}